// round 10
// baseline (speedup 1.0000x reference)
#include <cuda_runtime.h>

// img: [256, 3, 224, 224] f32, y_idx/x_idx: [256] i32.
// out[b,c,h,w] = img * (0 if h in [y,y+32) && w in [x,x+32) else 1)
//
// R3 champion structure (tiled 32-row blocks, 8 front-batched float4
// loads/thread, __ldcs/__stcs) + __launch_bounds__(224, 7): cap regs at 41
// so 7 CTAs fit per SM instead of 6 -> +17% resident warps / bytes-in-flight.

#define SQ 32
#define BATCH 256
#define CH 3
#define HH 224
#define WW 224
#define W4 (WW / 4)                    // 56 float4 per row
#define TY 4                           // threads in y
#define RPT 8                          // rows per thread
#define TILE_H (TY * RPT)              // 32 rows per block

__global__ __launch_bounds__(W4 * TY, 7)
void random_square_dropout_kernel(const float4* __restrict__ img,
                                  const int* __restrict__ y_idx,
                                  const int* __restrict__ x_idx,
                                  float4* __restrict__ out) {
    const int b  = blockIdx.z;
    const int c  = blockIdx.y;
    const int h0 = blockIdx.x * TILE_H + threadIdx.y;  // rows h0 + TY*k
    const int w4 = threadIdx.x;                        // 0..55

    const int y = __ldg(&y_idx[b]);
    const int x = __ldg(&x_idx[b]);

    // 32-bit indexing throughout (max index ~9.6M < 2^31).
    const int plane = (b * CH + c) * (HH * W4);
    const int base  = plane + h0 * W4 + w4;

    // Front-batched loads: 8 independent DRAM requests in flight per thread.
    float4 v[RPT];
#pragma unroll
    for (int k = 0; k < RPT; k++)
        v[k] = __ldcs(&img[base + k * (TY * W4)]);

    // Column in-square flags (constant across this thread's rows).
    const int w0 = w4 * 4;
    const bool cx0 = (unsigned)(w0     - x) < SQ;
    const bool cx1 = (unsigned)(w0 + 1 - x) < SQ;
    const bool cx2 = (unsigned)(w0 + 2 - x) < SQ;
    const bool cx3 = (unsigned)(w0 + 3 - x) < SQ;

    if (cx0 || cx1 || cx2 || cx3) {
#pragma unroll
        for (int k = 0; k < RPT; k++) {
            const int h = h0 + k * TY;
            if ((unsigned)(h - y) < SQ) {
                if (cx0) v[k].x = 0.f;
                if (cx1) v[k].y = 0.f;
                if (cx2) v[k].z = 0.f;
                if (cx3) v[k].w = 0.f;
            }
        }
    }

#pragma unroll
    for (int k = 0; k < RPT; k++)
        __stcs(&out[base + k * (TY * W4)], v[k]);
}

extern "C" void kernel_launch(void* const* d_in, const int* in_sizes, int n_in,
                              void* d_out, int out_size) {
    const float4* img = (const float4*)d_in[0];
    const int* y_idx  = (const int*)d_in[1];
    const int* x_idx  = (const int*)d_in[2];
    float4* out       = (float4*)d_out;

    dim3 block(W4, TY);                      // 56 x 4 = 224 threads
    dim3 grid(HH / TILE_H, CH, BATCH);       // 7 x 3 x 256 = 5376 blocks
    random_square_dropout_kernel<<<grid, block>>>(img, y_idx, x_idx, out);
}

// round 11
// speedup vs baseline: 1.1373x; 1.1373x over previous
#include <cuda_runtime.h>

// img: [256, 3, 224, 224] f32, y_idx/x_idx: [256] i32.
// out[b,c,h,w] = img * (0 if h in [y,y+32) && w in [x,x+32) else 1)
//
// FINAL (champion config, R3): HBM-streaming kernel at the measured mixed
// R/W ceiling (~6.1 TB/s). Tiled 32-row blocks; each thread front-batches
// 8 coalesced float4 loads (rows h0 + 4k), masks via predicated unsigned
// range checks, stores with streaming hint. 46 regs / 6 CTAs/SM is the
// optimum of the MLP-vs-occupancy trade (R10 showed reg-capping serializes
// the loads; R8 showed higher occupancy adds L1tex-queue spread).

#define SQ 32
#define BATCH 256
#define CH 3
#define HH 224
#define WW 224
#define W4 (WW / 4)                    // 56 float4 per row
#define TY 4                           // threads in y
#define RPT 8                          // rows per thread
#define TILE_H (TY * RPT)              // 32 rows per block

__global__ __launch_bounds__(W4 * TY)
void random_square_dropout_kernel(const float4* __restrict__ img,
                                  const int* __restrict__ y_idx,
                                  const int* __restrict__ x_idx,
                                  float4* __restrict__ out) {
    const int b  = blockIdx.z;
    const int c  = blockIdx.y;
    const int h0 = blockIdx.x * TILE_H + threadIdx.y;  // rows h0 + TY*k
    const int w4 = threadIdx.x;                        // 0..55

    const int y = __ldg(&y_idx[b]);
    const int x = __ldg(&x_idx[b]);

    const long plane = ((long)b * CH + c) * (long)(HH * W4);
    const long base  = plane + (long)h0 * W4 + w4;

    // Front-batched loads: 8 independent DRAM requests in flight per thread.
    float4 v[RPT];
#pragma unroll
    for (int k = 0; k < RPT; k++)
        v[k] = __ldcs(&img[base + (long)(k * TY) * W4]);

    // Column in-square flags (constant across this thread's rows).
    const int w0 = w4 * 4;
    const bool cx0 = (unsigned)(w0     - x) < SQ;
    const bool cx1 = (unsigned)(w0 + 1 - x) < SQ;
    const bool cx2 = (unsigned)(w0 + 2 - x) < SQ;
    const bool cx3 = (unsigned)(w0 + 3 - x) < SQ;

    if (cx0 || cx1 || cx2 || cx3) {
#pragma unroll
        for (int k = 0; k < RPT; k++) {
            const int h = h0 + k * TY;
            if ((unsigned)(h - y) < SQ) {
                if (cx0) v[k].x = 0.f;
                if (cx1) v[k].y = 0.f;
                if (cx2) v[k].z = 0.f;
                if (cx3) v[k].w = 0.f;
            }
        }
    }

#pragma unroll
    for (int k = 0; k < RPT; k++)
        __stcs(&out[base + (long)(k * TY) * W4], v[k]);
}

extern "C" void kernel_launch(void* const* d_in, const int* in_sizes, int n_in,
                              void* d_out, int out_size) {
    const float4* img = (const float4*)d_in[0];
    const int* y_idx  = (const int*)d_in[1];
    const int* x_idx  = (const int*)d_in[2];
    float4* out       = (float4*)d_out;

    dim3 block(W4, TY);                      // 56 x 4 = 224 threads
    dim3 grid(HH / TILE_H, CH, BATCH);       // 7 x 3 x 256 = 5376 blocks
    random_square_dropout_kernel<<<grid, block>>>(img, y_idx, x_idx, out);
}